// round 16
// baseline (speedup 1.0000x reference)
#include <cuda_runtime.h>
#include <cuda_bf16.h>
#include <math_constants.h>
#include <mma.h>
#include <cstdint>

using namespace nvcuda;

#define N_NODES 100000
#define N_EDGES 1600000
#define HID 64
#define HL 256
#define N_GRAPHS 512
#define SCAN_NB 98            // ceil(100000 / 1024)

// ======================= scratch =======================
__device__ int      g_deg[N_NODES];
__device__ int      g_row_ptr[N_NODES + 1];
__device__ int      g_cursor[N_NODES];
__device__ int      g_csr[N_EDGES];
__device__ int      g_blk[128];
__device__ int      g_blkoff[128];
__device__ __align__(256) float g_bufA[N_NODES * HID];
__device__ __align__(256) float g_bufB[N_NODES * HID];
__device__ __align__(256) float g_p[N_NODES * HID];       // aggregate buffer (fp32)
__device__ __align__(256) uint32_t g_hbf[N_NODES * 32];   // current layer input, bf16x2 packed
// weights: [layer][wr_hi, wr_lo, wq_hi, wq_lo][64 n][72 k] bf16 (transposed, padded)
__device__ __align__(256) __nv_bfloat16 g_wt[4][4][64 * 72];
__device__ float    g_sum[N_GRAPHS * HID];
__device__ unsigned g_maxenc[N_GRAPHS * HID];
__device__ float    g_cnt[N_GRAPHS];
__device__ float    g_o1[N_GRAPHS * HL];
__device__ float    g_o2[N_GRAPHS * HL];

__device__ __forceinline__ unsigned enc_f(float f) {
    unsigned b = __float_as_uint(f);
    return (b & 0x80000000u) ? ~b : (b | 0x80000000u);
}
__device__ __forceinline__ float dec_f(unsigned k) {
    unsigned b = (k & 0x80000000u) ? (k & 0x7FFFFFFFu) : ~k;
    return __uint_as_float(b);
}
#define ENC_NEGINF 0x007FFFFFu

// ======================= CSR build =======================
__global__ void k_zero() {
    int i = blockIdx.x * blockDim.x + threadIdx.x;
    if (i < N_NODES) g_deg[i] = 0;
    if (i < N_GRAPHS * HID) { g_sum[i] = 0.f; g_maxenc[i] = ENC_NEGINF; }
    if (i < N_GRAPHS) g_cnt[i] = 0.f;
}

// split weights into bf16 hi/lo, transposed to [n][k] with row stride 72
__global__ void k_wsplit(const float* __restrict__ w0r, const float* __restrict__ w0q,
                         const float* __restrict__ w1r, const float* __restrict__ w1q,
                         const float* __restrict__ w2r, const float* __restrict__ w2q,
                         const float* __restrict__ w3r, const float* __restrict__ w3q) {
    int i = blockIdx.x * blockDim.x + threadIdx.x;   // 0..32767
    if (i >= 4 * 2 * 4096) return;
    int l = i >> 13;
    int m = (i >> 12) & 1;           // 0 = wrel, 1 = wroot
    int e = i & 4095;
    int n = e >> 6, k = e & 63;
    const float* w;
    switch (l * 2 + m) {
        case 0: w = w0r; break; case 1: w = w0q; break;
        case 2: w = w1r; break; case 3: w = w1q; break;
        case 4: w = w2r; break; case 5: w = w2q; break;
        case 6: w = w3r; break; default: w = w3q; break;
    }
    float v = w[k * 64 + n];
    __nv_bfloat16 hi = __float2bfloat16(v);
    __nv_bfloat16 lo = __float2bfloat16(v - __bfloat162float(hi));
    g_wt[l][m * 2 + 0][n * 72 + k] = hi;
    g_wt[l][m * 2 + 1][n * 72 + k] = lo;
}

// one-time: x -> bf16x2 packed (layer-0 gather input)
__global__ void k_xbf16(const float* __restrict__ x) {
    int i = blockIdx.x * blockDim.x + threadIdx.x;
    if (i < N_NODES * 32) {
        float2 f = ((const float2*)x)[i];
        __nv_bfloat162 b = __float22bfloat162_rn(f);
        g_hbf[i] = *(uint32_t*)&b;
    }
}

__global__ void k_count(const int* __restrict__ dst) {
    int e = blockIdx.x * blockDim.x + threadIdx.x;
    if (e < N_EDGES) atomicAdd(&g_deg[dst[e]], 1);
}

// ---- 3-phase parallel scan of g_deg -> g_row_ptr / g_cursor ----
__global__ void __launch_bounds__(1024)
k_scan1() {
    __shared__ int sm[1024];
    const int tid = threadIdx.x;
    const int i = blockIdx.x * 1024 + tid;
    int v = (i < N_NODES) ? g_deg[i] : 0;
    sm[tid] = v;
    __syncthreads();
#pragma unroll
    for (int off = 1; off < 1024; off <<= 1) {
        int t = (tid >= off) ? sm[tid - off] : 0;
        __syncthreads();
        sm[tid] += t;
        __syncthreads();
    }
    if (i < N_NODES) g_row_ptr[i] = sm[tid] - v;     // exclusive within block
    if (tid == 1023) g_blk[blockIdx.x] = sm[1023];   // block total
}

__global__ void __launch_bounds__(128)
k_scan2() {
    __shared__ int sm[128];
    const int tid = threadIdx.x;
    int v = (tid < SCAN_NB) ? g_blk[tid] : 0;
    sm[tid] = v;
    __syncthreads();
#pragma unroll
    for (int off = 1; off < 128; off <<= 1) {
        int t = (tid >= off) ? sm[tid - off] : 0;
        __syncthreads();
        sm[tid] += t;
        __syncthreads();
    }
    if (tid < SCAN_NB) g_blkoff[tid] = sm[tid] - v;  // exclusive block offset
    if (tid == SCAN_NB - 1) g_row_ptr[N_NODES] = sm[tid];
}

__global__ void __launch_bounds__(1024)
k_scan3() {
    const int i = blockIdx.x * 1024 + threadIdx.x;
    if (i < N_NODES) {
        int r = g_row_ptr[i] + g_blkoff[blockIdx.x];
        g_row_ptr[i] = r;
        g_cursor[i]  = r;
    }
}

__global__ void k_scatter(const int* __restrict__ src, const int* __restrict__ dst) {
    int e = blockIdx.x * blockDim.x + threadIdx.x;
    if (e < N_EDGES) {
        int d = dst[e];
        int pos = atomicAdd(&g_cursor[d], 1);
        g_csr[pos] = src[e];
    }
}

// ===================== aggregation: g_p[i] = sum_{j->i} bf16(h[j]) ============
// 32-lane gather, ONE uint32 (2 x bf16) per lane per edge = 1 cache line/row.
__global__ void __launch_bounds__(256)
k_agg()
{
    int warp = (blockIdx.x * blockDim.x + threadIdx.x) >> 5;
    int lane = threadIdx.x & 31;
    if (warp >= N_NODES) return;
    const int s0 = g_row_ptr[warp];
    const int s1 = g_row_ptr[warp + 1];

    const uint32_t* __restrict__ hb = g_hbf;
    float2 acc = make_float2(0.f, 0.f);

    for (int b = s0; b < s1; b += 32) {
        int j = (b + lane < s1) ? g_csr[b + lane] : 0;
        int cnt = min(32, s1 - b);
#pragma unroll 8
        for (int t = 0; t < cnt; t++) {
            int jj = __shfl_sync(0xffffffffu, j, t);
            uint32_t u = __ldg(&hb[jj * 32 + lane]);
            __nv_bfloat162 bv = *(__nv_bfloat162*)&u;
            float2 f = __bfloat1622float2(bv);
            acc.x += f.x;
            acc.y += f.y;
        }
    }
    ((float2*)g_p)[warp * 32 + lane] = acc;
}

// ====== fused dense (WMMA bf16x3): hout = act(agg@Wrel + b + h@Wroot) =========
// 128 nodes / block, 256 threads (8 warps). Each warp: 16 rows x 64 cols.
// smem: bias(256 B) | A panes 4 x 18432 B (128x72 bf16) | W panes 4 x 9216 B.
// C staging reuses the A-pane region after a block sync (8 x 4096 B = 32 KB).
#define AST      72                     // A/W row stride (bf16 elems)
#define APANE    (128 * AST * 2)        // 18432 B
#define WPANE    (64 * AST * 2)         // 9216 B
#define SM_A     256
#define SM_W     (SM_A + 4 * APANE)     // 73984
#define SM_TOTAL (SM_W + 4 * WPANE)     // 110848 B

__global__ void __launch_bounds__(256)
k_dense_mma(const float* __restrict__ x, const float* __restrict__ brel,
            int layer, int inSel, int outSel, int doRelu)
{
    extern __shared__ char smem[];
    const float* hin = (inSel == 0) ? x : (inSel == 1 ? g_bufA : g_bufB);
    float* hout = (outSel == 1) ? g_bufA : g_bufB;

    const int tid  = threadIdx.x;
    const int wid  = tid >> 5;
    const int lane = tid & 31;
    const int base = blockIdx.x * 128;

    if (tid < 64) ((float*)smem)[tid] = brel[tid];

    // weights: raw 36 KB copy (pre-split/transposed/padded in g_wt)
    {
        const uint4* wsrc = (const uint4*)&g_wt[layer][0][0];
        uint4* wdst = (uint4*)(smem + SM_W);
#pragma unroll
        for (int i = 0; i < 9; i++) wdst[tid + i * 256] = wsrc[tid + i * 256];
    }

    // A panes: convert agg (g_p) and h to bf16 hi/lo. 2048 chunks of 8 cols.
#pragma unroll
    for (int c = 0; c < 8; c++) {
        int idx = tid + c * 256;
        int mat = idx >> 10;             // 0 = agg, 1 = h
        int e = idx & 1023;
        int row = e >> 3;
        int c8 = (e & 7) * 8;
        int node = base + row;
        const float* src = mat ? hin : g_p;
        float4 v0, v1;
        if (node < N_NODES) {
            v0 = ((const float4*)src)[node * 16 + (c8 >> 2)];
            v1 = ((const float4*)src)[node * 16 + (c8 >> 2) + 1];
        } else {
            v0 = make_float4(0.f, 0.f, 0.f, 0.f);
            v1 = v0;
        }
        float v[8] = {v0.x, v0.y, v0.z, v0.w, v1.x, v1.y, v1.z, v1.w};
        uint32_t hu[4], lu[4];
#pragma unroll
        for (int j = 0; j < 4; j++) {
            float2 f = make_float2(v[2 * j], v[2 * j + 1]);
            __nv_bfloat162 h2 = __float22bfloat162_rn(f);
            float2 hf = __bfloat1622float2(h2);
            __nv_bfloat162 l2 = __float22bfloat162_rn(
                make_float2(f.x - hf.x, f.y - hf.y));
            hu[j] = *(uint32_t*)&h2;
            lu[j] = *(uint32_t*)&l2;
        }
        char* hb = smem + SM_A + (mat ? 2 : 0) * APANE;   // hi pane
        char* lb = hb + APANE;                            // lo pane
        uint32_t off = (uint32_t)(row * (AST * 2) + c8 * 2);
        *(uint4*)(hb + off) = make_uint4(hu[0], hu[1], hu[2], hu[3]);
        *(uint4*)(lb + off) = make_uint4(lu[0], lu[1], lu[2], lu[3]);
    }
    __syncthreads();

    wmma::fragment<wmma::accumulator, 16, 16, 16, float> acc[4];
#pragma unroll
    for (int nt = 0; nt < 4; nt++) wmma::fill_fragment(acc[nt], 0.f);

    const int apane[6] = {0, 0, 1, 2, 2, 3};   // agg_hi, agg_hi, agg_lo, h_hi, h_hi, h_lo
    const int wpane[6] = {0, 1, 0, 2, 3, 2};   // wr_hi,  wr_lo,  wr_hi,  wq_hi, wq_lo, wq_hi

#pragma unroll
    for (int p = 0; p < 6; p++) {
        const __nv_bfloat16* pA =
            (const __nv_bfloat16*)(smem + SM_A + apane[p] * APANE) + wid * 16 * AST;
        const __nv_bfloat16* pW =
            (const __nv_bfloat16*)(smem + SM_W + wpane[p] * WPANE);
#pragma unroll
        for (int k0 = 0; k0 < 4; k0++) {
            wmma::fragment<wmma::matrix_a, 16, 16, 16, __nv_bfloat16, wmma::row_major> af;
            wmma::load_matrix_sync(af, pA + k0 * 16, AST);
#pragma unroll
            for (int nt = 0; nt < 4; nt++) {
                wmma::fragment<wmma::matrix_b, 16, 16, 16, __nv_bfloat16, wmma::col_major> bf;
                wmma::load_matrix_sync(bf, pW + nt * 16 * AST + k0 * 16, AST);
                wmma::mma_sync(acc[nt], af, bf, acc[nt]);
            }
        }
    }

    // stage C to smem (reuse A-pane region), then bias + relu + store fp32 + bf16
    __syncthreads();
    float* cst = (float*)(smem + SM_A) + wid * 16 * 64;
#pragma unroll
    for (int nt = 0; nt < 4; nt++)
        wmma::store_matrix_sync(cst + nt * 16, acc[nt], 64, wmma::mem_row_major);
    __syncwarp();

    const float* bias = (const float*)smem;
    const int r  = lane >> 1;            // 0..15
    const int hf = (lane & 1) * 32;      // col half
    int node = base + wid * 16 + r;
    if (node < N_NODES) {
        float4* op = (float4*)&hout[node * 64];
        uint32_t* ob = &g_hbf[node * 32];
#pragma unroll
        for (int j = 0; j < 8; j++) {
            int c = hf + j * 4;
            float v0 = cst[r * 64 + c + 0] + bias[c + 0];
            float v1 = cst[r * 64 + c + 1] + bias[c + 1];
            float v2 = cst[r * 64 + c + 2] + bias[c + 2];
            float v3 = cst[r * 64 + c + 3] + bias[c + 3];
            if (doRelu) {
                v0 = fmaxf(v0, 0.f); v1 = fmaxf(v1, 0.f);
                v2 = fmaxf(v2, 0.f); v3 = fmaxf(v3, 0.f);
            }
            op[c >> 2] = make_float4(v0, v1, v2, v3);
            __nv_bfloat162 b0 = __float22bfloat162_rn(make_float2(v0, v1));
            __nv_bfloat162 b1 = __float22bfloat162_rn(make_float2(v2, v3));
            *(uint2*)&ob[c >> 1] = make_uint2(*(uint32_t*)&b0, *(uint32_t*)&b1);
        }
    }
}

// ===================== pooling (batch sorted: run-compress) ===================
__global__ void k_pool(const int* __restrict__ batch)
{
    const float* __restrict__ h = g_bufB;
    const int tx = threadIdx.x;
    const int ty = threadIdx.y;
    const int base = blockIdx.x * 256;
    const int lim = min(base + 256, N_NODES);

    int cur = -1;
    float lsum = 0.f, lmax = -CUDART_INF_F;
    int lcnt = 0;

    for (int n = base + ty; n < lim; n += 4) {
        int g = batch[n];
        if (g != cur) {
            if (cur >= 0) {
                atomicAdd(&g_sum[cur * 64 + tx], lsum);
                atomicMax(&g_maxenc[cur * 64 + tx], enc_f(lmax));
                if (tx == 0) atomicAdd(&g_cnt[cur], (float)lcnt);
            }
            cur = g; lsum = 0.f; lmax = -CUDART_INF_F; lcnt = 0;
        }
        float v = h[n * 64 + tx];
        lsum += v;
        lmax = fmaxf(lmax, v);
        lcnt++;
    }
    if (cur >= 0) {
        atomicAdd(&g_sum[cur * 64 + tx], lsum);
        atomicMax(&g_maxenc[cur * 64 + tx], enc_f(lmax));
        if (tx == 0) atomicAdd(&g_cnt[cur], (float)lcnt);
    }
}

// ===================== MLP head (8 graphs per block) ==========================
__global__ void __launch_bounds__(256)
k_mlp1(const float* __restrict__ T,
       const float* __restrict__ w1, const float* __restrict__ b1)
{
    __shared__ float feat[8][208];
    const int g0 = blockIdx.x * 8;
    const int t = threadIdx.x;
    for (int i = t; i < 8 * 208; i += 256) {
        int gi = i / 208, f = i % 208;
        int g = g0 + gi;
        float val = 0.f;
        if (f < 64) {
            float m = dec_f(g_maxenc[g * 64 + f]);
            val = isfinite(m) ? m : 0.f;
        } else if (f < 128) {
            val = g_sum[g * 64 + (f - 64)] / fmaxf(g_cnt[g], 1.f);
        } else if (f < 192) {
            val = g_sum[g * 64 + (f - 128)];
        } else if (f == 192) {
            val = T[g];
        }
        feat[gi][f] = val;
    }
    __syncthreads();
    float acc[8];
    float bb = b1[t];
#pragma unroll
    for (int gi = 0; gi < 8; gi++) acc[gi] = bb;
    for (int k = 0; k < 193; k++) {
        float wv = w1[k * HL + t];
#pragma unroll
        for (int gi = 0; gi < 8; gi++) acc[gi] = fmaf(feat[gi][k], wv, acc[gi]);
    }
#pragma unroll
    for (int gi = 0; gi < 8; gi++)
        g_o1[(g0 + gi) * HL + t] = fmaxf(acc[gi], 0.f);
}

__global__ void __launch_bounds__(256)
k_mlp2(const float* __restrict__ w2, const float* __restrict__ b2)
{
    __shared__ float feat[8][HL];
    const int g0 = blockIdx.x * 8;
    const int t = threadIdx.x;
#pragma unroll
    for (int gi = 0; gi < 8; gi++)
        feat[gi][t] = g_o1[(g0 + gi) * HL + t];
    __syncthreads();
    float acc[8];
    float bb = b2[t];
#pragma unroll
    for (int gi = 0; gi < 8; gi++) acc[gi] = bb;
    for (int k = 0; k < HL; k++) {
        float wv = w2[k * HL + t];
#pragma unroll
        for (int gi = 0; gi < 8; gi++) acc[gi] = fmaf(feat[gi][k], wv, acc[gi]);
    }
#pragma unroll
    for (int gi = 0; gi < 8; gi++)
        g_o2[(g0 + gi) * HL + t] = fmaxf(acc[gi], 0.f);
}

__global__ void __launch_bounds__(256)
k_mlp3(const float* __restrict__ w3, const float* __restrict__ b3,
       float* __restrict__ out)
{
    __shared__ float red[256];
    const int g = blockIdx.x;
    const int t = threadIdx.x;
    red[t] = g_o2[g * HL + t] * w3[t];
    __syncthreads();
    for (int s = 128; s > 0; s >>= 1) {
        if (t < s) red[t] += red[t + s];
        __syncthreads();
    }
    if (t == 0) out[g] = red[0] + b3[0];
}

// ===================== launch =================================================
extern "C" void kernel_launch(void* const* d_in, const int* in_sizes, int n_in,
                              void* d_out, int out_size)
{
    const float* x     = (const float*)d_in[0];
    const int*   ei    = (const int*)  d_in[1];
    const int*   batch = (const int*)  d_in[2];
    const float* T     = (const float*)d_in[3];
    const float* wrel[4]  = {(const float*)d_in[4],  (const float*)d_in[7],
                             (const float*)d_in[10], (const float*)d_in[13]};
    const float* brel[4]  = {(const float*)d_in[5],  (const float*)d_in[8],
                             (const float*)d_in[11], (const float*)d_in[14]};
    const float* wroot[4] = {(const float*)d_in[6],  (const float*)d_in[9],
                             (const float*)d_in[12], (const float*)d_in[15]};
    const float* w1 = (const float*)d_in[16];
    const float* b1 = (const float*)d_in[17];
    const float* w2 = (const float*)d_in[18];
    const float* b2 = (const float*)d_in[19];
    const float* w3 = (const float*)d_in[20];
    const float* b3 = (const float*)d_in[21];
    float* out = (float*)d_out;

    const int* src = ei;
    const int* dst = ei + N_EDGES;

    cudaFuncSetAttribute(k_dense_mma, cudaFuncAttributeMaxDynamicSharedMemorySize,
                         SM_TOTAL);

    // CSR build + weight splitting + x -> bf16
    k_zero<<<(N_NODES + 255) / 256, 256>>>();
    k_wsplit<<<(4 * 2 * 4096 + 255) / 256, 256>>>(wrel[0], wroot[0], wrel[1], wroot[1],
                                                  wrel[2], wroot[2], wrel[3], wroot[3]);
    k_xbf16<<<(N_NODES * 32 + 255) / 256, 256>>>(x);
    k_count<<<(N_EDGES + 255) / 256, 256>>>(dst);
    k_scan1<<<SCAN_NB, 1024>>>();
    k_scan2<<<1, 128>>>();
    k_scan3<<<SCAN_NB, 1024>>>();
    k_scatter<<<(N_EDGES + 255) / 256, 256>>>(src, dst);

    const int AGG_GRID   = (N_NODES * 32 + 255) / 256;
    const int DENSE_GRID = (N_NODES + 127) / 128;

    // layer 0: gather bf16(x) -> g_p ; fused dense(x) -> bufA (+bf16), relu
    k_agg<<<AGG_GRID, 256>>>();
    k_dense_mma<<<DENSE_GRID, 256, SM_TOTAL>>>(x, brel[0], 0, 0, 1, 1);
    // layer 1: bufA -> bufB, relu
    k_agg<<<AGG_GRID, 256>>>();
    k_dense_mma<<<DENSE_GRID, 256, SM_TOTAL>>>(x, brel[1], 1, 1, 2, 1);
    // layer 2: bufB -> bufA, relu
    k_agg<<<AGG_GRID, 256>>>();
    k_dense_mma<<<DENSE_GRID, 256, SM_TOTAL>>>(x, brel[2], 2, 2, 1, 1);
    // layer 3: bufA -> bufB, no relu
    k_agg<<<AGG_GRID, 256>>>();
    k_dense_mma<<<DENSE_GRID, 256, SM_TOTAL>>>(x, brel[3], 3, 1, 2, 0);

    // pooling + MLP head
    dim3 pb(64, 4);
    k_pool<<<(N_NODES + 255) / 256, pb>>>(batch);
    k_mlp1<<<N_GRAPHS / 8, 256>>>(T, w1, b1);
    k_mlp2<<<N_GRAPHS / 8, 256>>>(w2, b2);
    k_mlp3<<<N_GRAPHS, 256>>>(w3, b3, out);
}

// round 17
// speedup vs baseline: 1.0929x; 1.0929x over previous
#include <cuda_runtime.h>
#include <cuda_bf16.h>
#include <math_constants.h>
#include <mma.h>
#include <cstdint>

using namespace nvcuda;

#define N_NODES 100000
#define N_EDGES 1600000
#define HID 64
#define HL 256
#define N_GRAPHS 512
#define SCAN_NB 98            // ceil(100000 / 1024)

// ======================= scratch =======================
__device__ int      g_deg[N_NODES];
__device__ int      g_row_ptr[N_NODES + 1];
__device__ int      g_cursor[N_NODES];
__device__ int      g_csr[N_EDGES];
__device__ int      g_blk[128];
__device__ int      g_blkoff[128];
__device__ __align__(256) float g_bufA[N_NODES * HID];
__device__ __align__(256) float g_bufB[N_NODES * HID];
__device__ __align__(256) float g_p[N_NODES * HID];       // aggregate buffer
// weights: [layer][wr_hi, wr_lo, wq_hi, wq_lo][64 n][72 k] bf16 (transposed, padded)
__device__ __align__(256) __nv_bfloat16 g_wt[4][4][64 * 72];
__device__ float    g_sum[N_GRAPHS * HID];
__device__ unsigned g_maxenc[N_GRAPHS * HID];
__device__ float    g_cnt[N_GRAPHS];
__device__ float    g_o1[N_GRAPHS * HL];
__device__ float    g_o2[N_GRAPHS * HL];

__device__ __forceinline__ unsigned enc_f(float f) {
    unsigned b = __float_as_uint(f);
    return (b & 0x80000000u) ? ~b : (b | 0x80000000u);
}
__device__ __forceinline__ float dec_f(unsigned k) {
    unsigned b = (k & 0x80000000u) ? (k & 0x7FFFFFFFu) : ~k;
    return __uint_as_float(b);
}
#define ENC_NEGINF 0x007FFFFFu

// ================= fused init: zero counters + split weights ==================
__global__ void k_init(const float* __restrict__ w0r, const float* __restrict__ w0q,
                       const float* __restrict__ w1r, const float* __restrict__ w1q,
                       const float* __restrict__ w2r, const float* __restrict__ w2q,
                       const float* __restrict__ w3r, const float* __restrict__ w3q) {
    int i = blockIdx.x * blockDim.x + threadIdx.x;   // 0..131071 (512 blocks x 256)
    if (i < N_NODES) g_deg[i] = 0;
    if (i < N_GRAPHS * HID) { g_sum[i] = 0.f; g_maxenc[i] = ENC_NEGINF; }
    if (i < N_GRAPHS) g_cnt[i] = 0.f;
    if (i < 4 * 2 * 4096) {
        int l = i >> 13;
        int m = (i >> 12) & 1;           // 0 = wrel, 1 = wroot
        int e = i & 4095;
        int n = e >> 6, k = e & 63;
        const float* w;
        switch (l * 2 + m) {
            case 0: w = w0r; break; case 1: w = w0q; break;
            case 2: w = w1r; break; case 3: w = w1q; break;
            case 4: w = w2r; break; case 5: w = w2q; break;
            case 6: w = w3r; break; default: w = w3q; break;
        }
        float v = w[k * 64 + n];
        __nv_bfloat16 hi = __float2bfloat16(v);
        __nv_bfloat16 lo = __float2bfloat16(v - __bfloat162float(hi));
        g_wt[l][m * 2 + 0][n * 72 + k] = hi;
        g_wt[l][m * 2 + 1][n * 72 + k] = lo;
    }
}

__global__ void k_count(const int* __restrict__ dst) {
    int e = blockIdx.x * blockDim.x + threadIdx.x;
    if (e < N_EDGES) atomicAdd(&g_deg[dst[e]], 1);
}

// ---- 3-phase parallel scan of g_deg -> g_row_ptr / g_cursor ----
__global__ void __launch_bounds__(1024)
k_scan1() {
    __shared__ int sm[1024];
    const int tid = threadIdx.x;
    const int i = blockIdx.x * 1024 + tid;
    int v = (i < N_NODES) ? g_deg[i] : 0;
    sm[tid] = v;
    __syncthreads();
#pragma unroll
    for (int off = 1; off < 1024; off <<= 1) {
        int t = (tid >= off) ? sm[tid - off] : 0;
        __syncthreads();
        sm[tid] += t;
        __syncthreads();
    }
    if (i < N_NODES) g_row_ptr[i] = sm[tid] - v;     // exclusive within block
    if (tid == 1023) g_blk[blockIdx.x] = sm[1023];   // block total
}

__global__ void __launch_bounds__(128)
k_scan2() {
    __shared__ int sm[128];
    const int tid = threadIdx.x;
    int v = (tid < SCAN_NB) ? g_blk[tid] : 0;
    sm[tid] = v;
    __syncthreads();
#pragma unroll
    for (int off = 1; off < 128; off <<= 1) {
        int t = (tid >= off) ? sm[tid - off] : 0;
        __syncthreads();
        sm[tid] += t;
        __syncthreads();
    }
    if (tid < SCAN_NB) g_blkoff[tid] = sm[tid] - v;  // exclusive block offset
    if (tid == SCAN_NB - 1) g_row_ptr[N_NODES] = sm[tid];
}

__global__ void __launch_bounds__(1024)
k_scan3() {
    const int i = blockIdx.x * 1024 + threadIdx.x;
    if (i < N_NODES) {
        int r = g_row_ptr[i] + g_blkoff[blockIdx.x];
        g_row_ptr[i] = r;
        g_cursor[i]  = r;
    }
}

__global__ void k_scatter(const int* __restrict__ src, const int* __restrict__ dst) {
    int e = blockIdx.x * blockDim.x + threadIdx.x;
    if (e < N_EDGES) {
        int d = dst[e];
        int pos = atomicAdd(&g_cursor[d], 1);
        g_csr[pos] = src[e];
    }
}

// ===================== aggregation: g_p[i] = sum_{j->i} h[j] ==================
// 2 edges per iteration: half-warps gather different edges as float4 rows.
__global__ void __launch_bounds__(256)
k_agg(const float* __restrict__ x, int inSel)
{
    const float* hin = (inSel == 0) ? x : (inSel == 1 ? g_bufA : g_bufB);
    int warp = (blockIdx.x * blockDim.x + threadIdx.x) >> 5;
    int lane = threadIdx.x & 31;
    if (warp >= N_NODES) return;
    const int s0 = g_row_ptr[warp];
    const int s1 = g_row_ptr[warp + 1];
    const int half = lane >> 4;      // 0 / 1
    const int l16  = lane & 15;      // col group (4 floats each)

    const float4* __restrict__ h4 = (const float4*)hin;
    float4 acc = make_float4(0.f, 0.f, 0.f, 0.f);

    for (int b = s0; b < s1; b += 32) {
        int j = (b + lane < s1) ? g_csr[b + lane] : 0;
        int cnt = min(32, s1 - b);
        int pairs = cnt & ~1;
#pragma unroll 4
        for (int t = 0; t < pairs; t += 2) {
            int jj = __shfl_sync(0xffffffffu, j, t + half);
            float4 v = __ldg(&h4[jj * 16 + l16]);
            acc.x += v.x; acc.y += v.y; acc.z += v.z; acc.w += v.w;
        }
        if (pairs < cnt) {           // odd tail: half 0 only
            int jj = __shfl_sync(0xffffffffu, j, pairs);
            if (half == 0) {
                float4 v = __ldg(&h4[jj * 16 + l16]);
                acc.x += v.x; acc.y += v.y; acc.z += v.z; acc.w += v.w;
            }
        }
    }
    // combine halves
    acc.x += __shfl_down_sync(0xffffffffu, acc.x, 16);
    acc.y += __shfl_down_sync(0xffffffffu, acc.y, 16);
    acc.z += __shfl_down_sync(0xffffffffu, acc.z, 16);
    acc.w += __shfl_down_sync(0xffffffffu, acc.w, 16);
    if (half == 0) ((float4*)g_p)[warp * 16 + l16] = acc;
}

// ====== fused dense (WMMA bf16x3): hout = act(agg@Wrel + b + h@Wroot) =========
// 128 nodes / block, 256 threads (8 warps). Each warp: 16 rows x 64 cols.
// smem: bias(256 B) | A panes 4 x 18432 B (128x72 bf16) | W panes 4 x 9216 B.
// C staging reuses the A-pane region after a block sync (8 x 4096 B = 32 KB).
#define AST      72                     // A/W row stride (bf16 elems)
#define APANE    (128 * AST * 2)        // 18432 B
#define WPANE    (64 * AST * 2)         // 9216 B
#define SM_A     256
#define SM_W     (SM_A + 4 * APANE)     // 73984
#define SM_TOTAL (SM_W + 4 * WPANE)     // 110848 B

__global__ void __launch_bounds__(256)
k_dense_mma(const float* __restrict__ x, const float* __restrict__ brel,
            int layer, int inSel, int outSel, int doRelu)
{
    extern __shared__ char smem[];
    const float* hin = (inSel == 0) ? x : (inSel == 1 ? g_bufA : g_bufB);
    float* hout = (outSel == 1) ? g_bufA : g_bufB;

    const int tid  = threadIdx.x;
    const int wid  = tid >> 5;
    const int lane = tid & 31;
    const int base = blockIdx.x * 128;

    if (tid < 64) ((float*)smem)[tid] = brel[tid];

    // weights: raw 36 KB copy (pre-split/transposed/padded in g_wt)
    {
        const uint4* wsrc = (const uint4*)&g_wt[layer][0][0];
        uint4* wdst = (uint4*)(smem + SM_W);
#pragma unroll
        for (int i = 0; i < 9; i++) wdst[tid + i * 256] = wsrc[tid + i * 256];
    }

    // A panes: convert agg (g_p) and h to bf16 hi/lo. 2048 chunks of 8 cols.
#pragma unroll
    for (int c = 0; c < 8; c++) {
        int idx = tid + c * 256;
        int mat = idx >> 10;             // 0 = agg, 1 = h
        int e = idx & 1023;
        int row = e >> 3;
        int c8 = (e & 7) * 8;
        int node = base + row;
        const float* src = mat ? hin : g_p;
        float4 v0, v1;
        if (node < N_NODES) {
            v0 = ((const float4*)src)[node * 16 + (c8 >> 2)];
            v1 = ((const float4*)src)[node * 16 + (c8 >> 2) + 1];
        } else {
            v0 = make_float4(0.f, 0.f, 0.f, 0.f);
            v1 = v0;
        }
        float v[8] = {v0.x, v0.y, v0.z, v0.w, v1.x, v1.y, v1.z, v1.w};
        uint32_t hu[4], lu[4];
#pragma unroll
        for (int j = 0; j < 4; j++) {
            float2 f = make_float2(v[2 * j], v[2 * j + 1]);
            __nv_bfloat162 h2 = __float22bfloat162_rn(f);
            float2 hf = __bfloat1622float2(h2);
            __nv_bfloat162 l2 = __float22bfloat162_rn(
                make_float2(f.x - hf.x, f.y - hf.y));
            hu[j] = *(uint32_t*)&h2;
            lu[j] = *(uint32_t*)&l2;
        }
        char* hb = smem + SM_A + (mat ? 2 : 0) * APANE;   // hi pane
        char* lb = hb + APANE;                            // lo pane
        uint32_t off = (uint32_t)(row * (AST * 2) + c8 * 2);
        *(uint4*)(hb + off) = make_uint4(hu[0], hu[1], hu[2], hu[3]);
        *(uint4*)(lb + off) = make_uint4(lu[0], lu[1], lu[2], lu[3]);
    }
    __syncthreads();

    wmma::fragment<wmma::accumulator, 16, 16, 16, float> acc[4];
#pragma unroll
    for (int nt = 0; nt < 4; nt++) wmma::fill_fragment(acc[nt], 0.f);

    const int apane[6] = {0, 0, 1, 2, 2, 3};   // agg_hi, agg_hi, agg_lo, h_hi, h_hi, h_lo
    const int wpane[6] = {0, 1, 0, 2, 3, 2};   // wr_hi,  wr_lo,  wr_hi,  wq_hi, wq_lo, wq_hi

#pragma unroll
    for (int p = 0; p < 6; p++) {
        const __nv_bfloat16* pA =
            (const __nv_bfloat16*)(smem + SM_A + apane[p] * APANE) + wid * 16 * AST;
        const __nv_bfloat16* pW =
            (const __nv_bfloat16*)(smem + SM_W + wpane[p] * WPANE);
#pragma unroll
        for (int k0 = 0; k0 < 4; k0++) {
            wmma::fragment<wmma::matrix_a, 16, 16, 16, __nv_bfloat16, wmma::row_major> af;
            wmma::load_matrix_sync(af, pA + k0 * 16, AST);
#pragma unroll
            for (int nt = 0; nt < 4; nt++) {
                wmma::fragment<wmma::matrix_b, 16, 16, 16, __nv_bfloat16, wmma::col_major> bf;
                wmma::load_matrix_sync(bf, pW + nt * 16 * AST + k0 * 16, AST);
                wmma::mma_sync(acc[nt], af, bf, acc[nt]);
            }
        }
    }

    // stage C to smem (reuse A-pane region), then bias + relu + store
    __syncthreads();
    float* cst = (float*)(smem + SM_A) + wid * 16 * 64;
#pragma unroll
    for (int nt = 0; nt < 4; nt++)
        wmma::store_matrix_sync(cst + nt * 16, acc[nt], 64, wmma::mem_row_major);
    __syncwarp();

    const float* bias = (const float*)smem;
    const int r  = lane >> 1;            // 0..15
    const int hf = (lane & 1) * 32;      // col half
    int node = base + wid * 16 + r;
    if (node < N_NODES) {
        float4* op = (float4*)&hout[node * 64];
#pragma unroll
        for (int j = 0; j < 8; j++) {
            int c = hf + j * 4;
            float v0 = cst[r * 64 + c + 0] + bias[c + 0];
            float v1 = cst[r * 64 + c + 1] + bias[c + 1];
            float v2 = cst[r * 64 + c + 2] + bias[c + 2];
            float v3 = cst[r * 64 + c + 3] + bias[c + 3];
            if (doRelu) {
                v0 = fmaxf(v0, 0.f); v1 = fmaxf(v1, 0.f);
                v2 = fmaxf(v2, 0.f); v3 = fmaxf(v3, 0.f);
            }
            op[c >> 2] = make_float4(v0, v1, v2, v3);
        }
    }
}

// ===================== pooling (batch sorted: run-compress) ===================
__global__ void k_pool(const int* __restrict__ batch)
{
    const float* __restrict__ h = g_bufB;
    const int tx = threadIdx.x;
    const int ty = threadIdx.y;
    const int base = blockIdx.x * 256;
    const int lim = min(base + 256, N_NODES);

    int cur = -1;
    float lsum = 0.f, lmax = -CUDART_INF_F;
    int lcnt = 0;

    for (int n = base + ty; n < lim; n += 4) {
        int g = batch[n];
        if (g != cur) {
            if (cur >= 0) {
                atomicAdd(&g_sum[cur * 64 + tx], lsum);
                atomicMax(&g_maxenc[cur * 64 + tx], enc_f(lmax));
                if (tx == 0) atomicAdd(&g_cnt[cur], (float)lcnt);
            }
            cur = g; lsum = 0.f; lmax = -CUDART_INF_F; lcnt = 0;
        }
        float v = h[n * 64 + tx];
        lsum += v;
        lmax = fmaxf(lmax, v);
        lcnt++;
    }
    if (cur >= 0) {
        atomicAdd(&g_sum[cur * 64 + tx], lsum);
        atomicMax(&g_maxenc[cur * 64 + tx], enc_f(lmax));
        if (tx == 0) atomicAdd(&g_cnt[cur], (float)lcnt);
    }
}

// ===================== MLP head ===============================================
__global__ void __launch_bounds__(256)
k_mlp1(const float* __restrict__ T,
       const float* __restrict__ w1, const float* __restrict__ b1)
{
    __shared__ float feat[208];
    const int g = blockIdx.x;
    const int t = threadIdx.x;
    if (t < 64) {
        float m = dec_f(g_maxenc[g * 64 + t]);
        if (!isfinite(m)) m = 0.f;
        feat[t] = m;
    } else if (t < 128) {
        feat[t] = g_sum[g * 64 + (t - 64)] / fmaxf(g_cnt[g], 1.f);
    } else if (t < 192) {
        feat[t] = g_sum[g * 64 + (t - 128)];
    } else if (t == 192) {
        feat[192] = T[g];
    }
    __syncthreads();
    float acc = b1[t];
#pragma unroll 4
    for (int k = 0; k < 193; k++)
        acc = fmaf(feat[k], w1[k * HL + t], acc);
    g_o1[g * HL + t] = fmaxf(acc, 0.f);
}

__global__ void __launch_bounds__(256)
k_mlp2(const float* __restrict__ w2, const float* __restrict__ b2)
{
    __shared__ float feat[HL];
    const int g = blockIdx.x;
    const int t = threadIdx.x;
    feat[t] = g_o1[g * HL + t];
    __syncthreads();
    float acc = b2[t];
#pragma unroll 4
    for (int k = 0; k < HL; k++)
        acc = fmaf(feat[k], w2[k * HL + t], acc);
    g_o2[g * HL + t] = fmaxf(acc, 0.f);
}

__global__ void __launch_bounds__(256)
k_mlp3(const float* __restrict__ w3, const float* __restrict__ b3,
       float* __restrict__ out)
{
    __shared__ float red[256];
    const int g = blockIdx.x;
    const int t = threadIdx.x;
    red[t] = g_o2[g * HL + t] * w3[t];
    __syncthreads();
    for (int s = 128; s > 0; s >>= 1) {
        if (t < s) red[t] += red[t + s];
        __syncthreads();
    }
    if (t == 0) out[g] = red[0] + b3[0];
}

// ===================== launch =================================================
extern "C" void kernel_launch(void* const* d_in, const int* in_sizes, int n_in,
                              void* d_out, int out_size)
{
    const float* x     = (const float*)d_in[0];
    const int*   ei    = (const int*)  d_in[1];
    const int*   batch = (const int*)  d_in[2];
    const float* T     = (const float*)d_in[3];
    const float* wrel[4]  = {(const float*)d_in[4],  (const float*)d_in[7],
                             (const float*)d_in[10], (const float*)d_in[13]};
    const float* brel[4]  = {(const float*)d_in[5],  (const float*)d_in[8],
                             (const float*)d_in[11], (const float*)d_in[14]};
    const float* wroot[4] = {(const float*)d_in[6],  (const float*)d_in[9],
                             (const float*)d_in[12], (const float*)d_in[15]};
    const float* w1 = (const float*)d_in[16];
    const float* b1 = (const float*)d_in[17];
    const float* w2 = (const float*)d_in[18];
    const float* b2 = (const float*)d_in[19];
    const float* w3 = (const float*)d_in[20];
    const float* b3 = (const float*)d_in[21];
    float* out = (float*)d_out;

    const int* src = ei;
    const int* dst = ei + N_EDGES;

    cudaFuncSetAttribute(k_dense_mma, cudaFuncAttributeMaxDynamicSharedMemorySize,
                         SM_TOTAL);

    // fused init (zero + wsplit), then CSR build
    k_init<<<512, 256>>>(wrel[0], wroot[0], wrel[1], wroot[1],
                         wrel[2], wroot[2], wrel[3], wroot[3]);
    k_count<<<(N_EDGES + 255) / 256, 256>>>(dst);
    k_scan1<<<SCAN_NB, 1024>>>();
    k_scan2<<<1, 128>>>();
    k_scan3<<<SCAN_NB, 1024>>>();
    k_scatter<<<(N_EDGES + 255) / 256, 256>>>(src, dst);

    const int AGG_GRID   = (N_NODES * 32 + 255) / 256;
    const int DENSE_GRID = (N_NODES + 127) / 128;

    // layer 0: gather x -> g_p ; fused dense(x) -> bufA, relu
    k_agg<<<AGG_GRID, 256>>>(x, 0);
    k_dense_mma<<<DENSE_GRID, 256, SM_TOTAL>>>(x, brel[0], 0, 0, 1, 1);
    // layer 1: bufA -> bufB, relu
    k_agg<<<AGG_GRID, 256>>>(x, 1);
    k_dense_mma<<<DENSE_GRID, 256, SM_TOTAL>>>(x, brel[1], 1, 1, 2, 1);
    // layer 2: bufB -> bufA, relu
    k_agg<<<AGG_GRID, 256>>>(x, 2);
    k_dense_mma<<<DENSE_GRID, 256, SM_TOTAL>>>(x, brel[2], 2, 2, 1, 1);
    // layer 3: bufA -> bufB, no relu
    k_agg<<<AGG_GRID, 256>>>(x, 1);
    k_dense_mma<<<DENSE_GRID, 256, SM_TOTAL>>>(x, brel[3], 3, 1, 2, 0);

    // pooling + MLP head
    dim3 pb(64, 4);
    k_pool<<<(N_NODES + 255) / 256, pb>>>(batch);
    k_mlp1<<<N_GRAPHS, 256>>>(T, w1, b1);
    k_mlp2<<<N_GRAPHS, 256>>>(w2, b2);
    k_mlp3<<<N_GRAPHS, 256>>>(w3, b3, out);
}